// round 6
// baseline (speedup 1.0000x reference)
#include <cuda_runtime.h>
#include <cuda_fp16.h>
#include <cstdint>

#define KTAGS 256
#define NTH   512
#define NW    16
#define SMAX  1024
#define LN2F  0.69314718055994531f
#define PROW  132                      // padded partial row (uints)

// exp(transitions) as fp16 (128 KB static global).
__device__ __half d_ETh[KTAGS * KTAGS];

__global__ void crf_prep(const float* __restrict__ trans) {
    int i = blockIdx.x * blockDim.x + threadIdx.x;
    if (i < KTAGS * KTAGS) d_ETh[i] = __float2half(expf(trans[i]));
}

__device__ __forceinline__ __half2 u2h(unsigned int u) { __half2 h; *(unsigned int*)&h = u; return h; }
__device__ __forceinline__ unsigned int h2u(__half2 h) { return *(unsigned int*)&h; }

__global__ __launch_bounds__(NTH, 1)
void crf_main(const float* __restrict__ emissions,
              const int* __restrict__ targets,
              const int* __restrict__ masks,
              const float* __restrict__ start_t,
              const float* __restrict__ end_t,
              const float* __restrict__ trans,
              float* __restrict__ out,
              int S)
{
    __shared__ unsigned int part[2 * NW * PROW];     // [par][group g][colpair c] padded
    __shared__ __align__(16) float ws[2][NW];        // per-warp sums of post-scale p
    __shared__ unsigned int pvec[KTAGS / 2];         // p as pair-half2 (tags 2c,2c+1)
    __shared__ float red[NW];
    __shared__ float rscr[NTH], cscr[NTH];
    __shared__ float num_smem;
    __shared__ int ms[SMAX];

    const int tid = threadIdx.x, b = blockIdx.x;
    const int lane = tid & 31, wid = tid >> 5;
    const int hp = lane >> 2, sg = lane & 3;
    const int c = 8 * wid + hp;                       // my colpair (dup x4 over sg)

    const float* emb  = emissions + (size_t)b * S * KTAGS;
    const int*   tg   = targets  + (size_t)b * S;
    const int*   mrow = masks    + (size_t)b * S;

    // ---- ET slice into regs: rows [16*wid,16*wid+16), colpairs [4*lane,4*lane+4) ----
    unsigned int et[16][4];
    {
        const uint4* etg = (const uint4*)d_ETh;       // 32 uint4 per row
        #pragma unroll
        for (int ii = 0; ii < 16; ii++) {
            uint4 v = etg[(size_t)(wid * 16 + ii) * 32 + lane];
            et[ii][0] = v.x; et[ii][1] = v.y; et[ii][2] = v.z; et[ii][3] = v.w;
        }
    }

    // ---- masks into SMEM ----
    for (int t = tid; t < S && t < SMAX; t += NTH) ms[t] = mrow[t];

    // ---- Numerator ----
    float npart = 0.f; int cnt = 0;
    for (int t = tid; t < S; t += NTH) {
        int m = mrow[t] != 0; cnt += m;
        if (t >= 1 && m) {
            int pv = tg[t - 1], cu = tg[t];
            npart += trans[pv * KTAGS + cu] + emb[(size_t)t * KTAGS + cu];
        }
    }
    rscr[tid] = npart; cscr[tid] = (float)cnt;
    __syncthreads();
    if (tid == 0) {
        float tot = 0.f, cc = 0.f;
        for (int i = 0; i < NTH; i++) { tot += rscr[i]; cc += cscr[i]; }
        int seq_end = (int)cc - 1; int t0 = tg[0];
        num_smem = tot + start_t[t0] + emb[t0] + end_t[tg[seq_end]];
    }

    // ---- Init (t = 0): exact max-normalization once ----
    float2 st2 = ((const float2*)start_t)[c];
    float2 e02 = ((const float2*)emb)[c];
    float s0a = st2.x + e02.x, s0b = st2.y + e02.y;
    float m = fmaxf(s0a, s0b);
    #pragma unroll
    for (int o = 16; o > 0; o >>= 1) m = fmaxf(m, __shfl_xor_sync(0xffffffffu, m, o));
    if (lane == 0) red[wid] = m;
    __syncthreads();
    float M = red[0];
    #pragma unroll
    for (int w = 1; w < NW; w++) M = fmaxf(M, red[w]);
    float p0 = __expf(s0a - M), p1 = __expf(s0b - M);
    int ktot = 0;

    pvec[c] = h2u(__floats2half2_rn(p0, p1));        // 4 dup lanes write same value
    float psum = p0 + p1;
    #pragma unroll
    for (int o = 16; o > 0; o >>= 1) psum += __shfl_xor_sync(0xffffffffu, psum, o);
    if (lane == 0) ws[0][wid] = psum * 0.25f;        // dup x4 correction
    __syncwarp();

    // ---- matvec for step 0 into part[0] ----
    {
        __half2 a0 = u2h(0u), a1 = u2h(0u), a2 = u2h(0u), a3 = u2h(0u);
        const uint4* pv4 = (const uint4*)(pvec + 8 * wid);
        #pragma unroll
        for (int h = 0; h < 2; h++) {
            uint4 v = pv4[h];
            unsigned int uu[4] = {v.x, v.y, v.z, v.w};
            #pragma unroll
            for (int j = 0; j < 4; j++) {
                __half2 pj = u2h(uu[j]);
                __half2 qlo = __low2half2(pj), qhi = __high2half2(pj);
                int r = h * 8 + j * 2;
                a0 = __hfma2(u2h(et[r][0]), qlo, a0);
                a1 = __hfma2(u2h(et[r][1]), qlo, a1);
                a2 = __hfma2(u2h(et[r][2]), qlo, a2);
                a3 = __hfma2(u2h(et[r][3]), qlo, a3);
                a0 = __hfma2(u2h(et[r+1][0]), qhi, a0);
                a1 = __hfma2(u2h(et[r+1][1]), qhi, a1);
                a2 = __hfma2(u2h(et[r+1][2]), qhi, a2);
                a3 = __hfma2(u2h(et[r+1][3]), qhi, a3);
            }
        }
        *(uint4*)(part + (size_t)wid * PROW + 4 * lane) =
            make_uint4(h2u(a0), h2u(a1), h2u(a2), h2u(a3));
    }

    // emission pipeline: ee pair for t=1, raw pair for t=2
    float2 e1 = ((const float2*)(emb + (size_t)((1 < S) ? 1 : 0) * KTAGS))[c];
    float ee0 = __expf(e1.x), ee1 = __expf(e1.y);
    float2 eraw = ((const float2*)(emb + (size_t)((2 < S) ? 2 : (S - 1)) * KTAGS))[c];

    // ---- Forward recursion: one barrier per step ----
    for (int t = 1; t < S; t++) {
        const int par = t & 1, pre = par ^ 1;
        __syncthreads();

        int tn = (t + 2 < S) ? (t + 2) : (S - 1);
        float2 eraw2 = ((const float2*)(emb + (size_t)tn * KTAGS))[c];
        int msk = (t < SMAX) ? ms[t] : mrow[t];

        // reduce: my colpair over 16 groups; lane sums 4, then 2 intra-quad shuffles
        const unsigned int* pb = part + pre * (NW * PROW) + c;
        __half2 x0 = u2h(pb[(4 * sg + 0) * PROW]);
        __half2 x1 = u2h(pb[(4 * sg + 1) * PROW]);
        __half2 x2 = u2h(pb[(4 * sg + 2) * PROW]);
        __half2 x3 = u2h(pb[(4 * sg + 3) * PROW]);
        __half2 sv = __hadd2(__hadd2(x0, x1), __hadd2(x2, x3));
        sv = __hadd2(sv, u2h(__shfl_xor_sync(0xffffffffu, h2u(sv), 1)));
        sv = __hadd2(sv, u2h(__shfl_xor_sync(0xffffffffu, h2u(sv), 2)));
        float s0 = __low2float(sv), s1 = __high2float(sv);

        // lag-1 normalizer from previous step's post-scale p-sum
        float4 w0 = *(const float4*)&ws[pre][0];
        float4 w1 = *(const float4*)&ws[pre][4];
        float4 w2 = *(const float4*)&ws[pre][8];
        float4 w3 = *(const float4*)&ws[pre][12];
        float Sp = (((w0.x + w0.y) + (w0.z + w0.w)) + ((w1.x + w1.y) + (w1.z + w1.w)))
                 + (((w2.x + w2.y) + (w2.z + w2.w)) + ((w3.x + w3.y) + (w3.z + w3.w)));
        unsigned int sb = __float_as_uint(Sp);
        int ke = (int)(sb >> 23) - 119;                                   // ilogb+8
        float sf = __uint_as_float((unsigned int)(246 - (int)(sb >> 23)) << 23);

        float q0 = s0 * ee0, q1 = s1 * ee1;
        if (msk) { p0 = q0 * sf; p1 = q1 * sf; ktot += ke; }

        pvec[c] = h2u(__floats2half2_rn(p0, p1));
        float ps = p0 + p1;
        #pragma unroll
        for (int o = 16; o > 0; o >>= 1) ps += __shfl_xor_sync(0xffffffffu, ps, o);
        if (lane == 0) ws[par][wid] = ps * 0.25f;

        // promote emission pipeline (exp off critical path)
        ee0 = __expf(eraw.x); ee1 = __expf(eraw.y);
        eraw = eraw2;
        __syncwarp();

        // matvec over new p (warp-local rows)
        __half2 a0 = u2h(0u), a1 = u2h(0u), a2 = u2h(0u), a3 = u2h(0u);
        const uint4* pv4 = (const uint4*)(pvec + 8 * wid);
        #pragma unroll
        for (int h = 0; h < 2; h++) {
            uint4 v = pv4[h];
            unsigned int uu[4] = {v.x, v.y, v.z, v.w};
            #pragma unroll
            for (int j = 0; j < 4; j++) {
                __half2 pj = u2h(uu[j]);
                __half2 qlo = __low2half2(pj), qhi = __high2half2(pj);
                int r = h * 8 + j * 2;
                a0 = __hfma2(u2h(et[r][0]), qlo, a0);
                a1 = __hfma2(u2h(et[r][1]), qlo, a1);
                a2 = __hfma2(u2h(et[r][2]), qlo, a2);
                a3 = __hfma2(u2h(et[r][3]), qlo, a3);
                a0 = __hfma2(u2h(et[r+1][0]), qhi, a0);
                a1 = __hfma2(u2h(et[r+1][1]), qhi, a1);
                a2 = __hfma2(u2h(et[r+1][2]), qhi, a2);
                a3 = __hfma2(u2h(et[r+1][3]), qhi, a3);
            }
        }
        *(uint4*)(part + (size_t)(par * NW + wid) * PROW + 4 * lane) =
            make_uint4(h2u(a0), h2u(a1), h2u(a2), h2u(a3));
    }

    // ---- Final: denominator = M + ktot*ln2 + log(Sigma p * exp(end)) ----
    float2 en2 = ((const float2*)end_t)[c];
    float v = p0 * __expf(en2.x) + p1 * __expf(en2.y);
    #pragma unroll
    for (int o = 16; o > 0; o >>= 1) v += __shfl_xor_sync(0xffffffffu, v, o);
    if (lane == 0) red[wid] = v * 0.25f;             // dup x4 correction
    __syncthreads();
    if (tid == 0) {
        float tot = 0.f;
        #pragma unroll
        for (int w = 0; w < NW; w++) tot += red[w];
        out[b] = num_smem - (M + (float)ktot * LN2F + __logf(tot));
    }
}

extern "C" void kernel_launch(void* const* d_in, const int* in_sizes, int n_in,
                              void* d_out, int out_size) {
    const float* emissions = (const float*)d_in[0];
    const int*   targets   = (const int*)d_in[1];
    const int*   masks     = (const int*)d_in[2];
    const float* start_t   = (const float*)d_in[3];
    const float* end_t     = (const float*)d_in[4];
    const float* trans     = (const float*)d_in[5];
    float*       out       = (float*)d_out;

    int B = out_size;
    int S = in_sizes[1] / B;

    crf_prep<<<(KTAGS * KTAGS + 255) / 256, 256>>>(trans);
    crf_main<<<B, NTH>>>(emissions, targets, masks, start_t, end_t, trans, out, S);
}

// round 7
// speedup vs baseline: 1.7287x; 1.7287x over previous
#include <cuda_runtime.h>
#include <cuda_fp16.h>
#include <cstdint>

#define KTAGS 256
#define NTH   256
#define SMAX  1024
#define LN2F  0.69314718055994531f

// ET column-pair-major: d_ETp[c*128 + i] = half2( exp(T[2i][c]), exp(T[2i+1][c]) )
__device__ __half2 d_ETp[KTAGS * (KTAGS / 2)];

__global__ void crf_prep(const float* __restrict__ trans) {
    int idx = blockIdx.x * blockDim.x + threadIdx.x;   // 256*128 threads
    if (idx < KTAGS * (KTAGS / 2)) {
        int c = idx >> 7, i = idx & 127;
        float lo = expf(trans[(2 * i)     * KTAGS + c]);
        float hi = expf(trans[(2 * i + 1) * KTAGS + c]);
        d_ETp[idx] = __floats2half2_rn(lo, hi);
    }
}

__device__ __forceinline__ __half2 u2h(unsigned int u) { __half2 h; *(unsigned int*)&h = u; return h; }
__device__ __forceinline__ unsigned int h2u(__half2 h) { return *(unsigned int*)&h; }

__global__ __launch_bounds__(NTH, 1)
void crf_main(const float* __restrict__ emissions,
              const int* __restrict__ targets,
              const int* __restrict__ masks,
              const float* __restrict__ start_t,
              const float* __restrict__ end_t,
              const float* __restrict__ trans,
              float* __restrict__ out,
              int S)
{
    __shared__ __align__(16) unsigned int pvec[2][KTAGS / 2];  // p as half2 pairs, double-buffered
    __shared__ __align__(16) float ws[2][8];                   // per-warp sums of post-scale p
    __shared__ float red[8];
    __shared__ float rscr[NTH], cscr[NTH];
    __shared__ float num_smem;
    __shared__ int ms[SMAX];

    const int tid = threadIdx.x, b = blockIdx.x;
    const int lane = tid & 31, wid = tid >> 5;
    const int c = tid;                                  // my output column (tag)

    const float* emb  = emissions + (size_t)b * S * KTAGS;
    const int*   tg   = targets  + (size_t)b * S;
    const int*   mrow = masks    + (size_t)b * S;

    // ---- ET column c into registers: 128 half2 (row pairs) as 32 uint4 ----
    uint4 et4[32];
    {
        const uint4* etg = (const uint4*)(d_ETp + (size_t)c * 128);
        #pragma unroll
        for (int k = 0; k < 32; k++) et4[k] = etg[k];
    }

    // ---- masks into SMEM ----
    for (int t = tid; t < S && t < SMAX; t += NTH) ms[t] = mrow[t];

    // ---- Numerator ----
    float npart = 0.f; int cnt = 0;
    for (int t = tid; t < S; t += NTH) {
        int m = mrow[t] != 0; cnt += m;
        if (t >= 1 && m) {
            int pv = tg[t - 1], cu = tg[t];
            npart += trans[pv * KTAGS + cu] + emb[(size_t)t * KTAGS + cu];
        }
    }
    rscr[tid] = npart; cscr[tid] = (float)cnt;
    __syncthreads();
    if (tid == 0) {
        float tot = 0.f, cc = 0.f;
        for (int i = 0; i < NTH; i++) { tot += rscr[i]; cc += cscr[i]; }
        int seq_end = (int)cc - 1; int t0 = tg[0];
        num_smem = tot + start_t[t0] + emb[t0] + end_t[tg[seq_end]];
    }

    // ---- Init (t = 0): exact max-normalization once ----
    float s0 = start_t[c] + emb[c];
    float m = s0;
    #pragma unroll
    for (int o = 16; o > 0; o >>= 1) m = fmaxf(m, __shfl_xor_sync(0xffffffffu, m, o));
    if (lane == 0) red[wid] = m;
    __syncthreads();
    float M = red[0];
    #pragma unroll
    for (int w = 1; w < 8; w++) M = fmaxf(M, red[w]);
    float p = __expf(s0 - M);
    int ktot = 0;

    ((__half*)pvec[0])[c] = __float2half(p);
    float psum = p;
    #pragma unroll
    for (int o = 16; o > 0; o >>= 1) psum += __shfl_xor_sync(0xffffffffu, psum, o);
    if (lane == 0) ws[0][wid] = psum;

    // emission pipeline: ee = exp(e_t) for t=1, eraw = raw e for t=2
    float ee   = __expf(emb[(size_t)((1 < S) ? 1 : 0) * KTAGS + c]);
    float eraw = emb[(size_t)((2 < S) ? 2 : (S - 1)) * KTAGS + c];

    // ---- Forward recursion: one barrier per step ----
    for (int t = 1; t < S; t++) {
        const int par = t & 1, pre = par ^ 1;
        __syncthreads();

        int tn = (t + 2 < S) ? (t + 2) : (S - 1);
        float eraw2 = emb[(size_t)tn * KTAGS + c];
        int msk = (t < SMAX) ? ms[t] : mrow[t];

        // lag-1 normalizer from previous step's post-scale p-sum
        float4 w0 = *(const float4*)&ws[pre][0];
        float4 w1 = *(const float4*)&ws[pre][4];
        float Sp = ((w0.x + w0.y) + (w0.z + w0.w)) + ((w1.x + w1.y) + (w1.z + w1.w));
        unsigned int sb = __float_as_uint(Sp);
        int ke = (int)(sb >> 23) - 119;                                   // ilogb+8
        float sf = __uint_as_float((unsigned int)(246 - (int)(sb >> 23)) << 23);

        // matvec: ssum_c = sum_i p_i * ET[i][c], 8 independent fp16 chains
        __half2 a0 = u2h(0u), a1 = u2h(0u), a2 = u2h(0u), a3 = u2h(0u);
        __half2 a4 = u2h(0u), a5 = u2h(0u), a6 = u2h(0u), a7 = u2h(0u);
        const uint4* pv = (const uint4*)pvec[pre];      // 32 broadcast uint4
        #pragma unroll
        for (int k = 0; k < 32; k += 2) {
            uint4 q0 = pv[k];
            uint4 q1 = pv[k + 1];
            a0 = __hfma2(u2h(et4[k].x),     u2h(q0.x), a0);
            a1 = __hfma2(u2h(et4[k].y),     u2h(q0.y), a1);
            a2 = __hfma2(u2h(et4[k].z),     u2h(q0.z), a2);
            a3 = __hfma2(u2h(et4[k].w),     u2h(q0.w), a3);
            a4 = __hfma2(u2h(et4[k + 1].x), u2h(q1.x), a4);
            a5 = __hfma2(u2h(et4[k + 1].y), u2h(q1.y), a5);
            a6 = __hfma2(u2h(et4[k + 1].z), u2h(q1.z), a6);
            a7 = __hfma2(u2h(et4[k + 1].w), u2h(q1.w), a7);
        }
        __half2 sA = __hadd2(__hadd2(a0, a1), __hadd2(a2, a3));
        __half2 sB = __hadd2(__hadd2(a4, a5), __hadd2(a6, a7));
        float2 fA = __half22float2(sA);
        float2 fB = __half22float2(sB);
        float ssum = (fA.x + fA.y) + (fB.x + fB.y);

        float q = ssum * ee;
        if (msk) { p = q * sf; ktot += ke; }

        ((__half*)pvec[par])[c] = __float2half(p);

        // off-critical-path: warp p-sum for next step's normalizer + emission exp
        float ps = p;
        #pragma unroll
        for (int o = 16; o > 0; o >>= 1) ps += __shfl_xor_sync(0xffffffffu, ps, o);
        if (lane == 0) ws[par][wid] = ps;

        ee = __expf(eraw);
        eraw = eraw2;
    }

    // ---- Final: denominator = M + ktot*ln2 + log(Sigma p * exp(end)) ----
    float v = p * __expf(end_t[c]);
    #pragma unroll
    for (int o = 16; o > 0; o >>= 1) v += __shfl_xor_sync(0xffffffffu, v, o);
    if (lane == 0) red[wid] = v;
    __syncthreads();
    if (tid == 0) {
        float tot = 0.f;
        #pragma unroll
        for (int w = 0; w < 8; w++) tot += red[w];
        out[b] = num_smem - (M + (float)ktot * LN2F + __logf(tot));
    }
}

extern "C" void kernel_launch(void* const* d_in, const int* in_sizes, int n_in,
                              void* d_out, int out_size) {
    const float* emissions = (const float*)d_in[0];
    const int*   targets   = (const int*)d_in[1];
    const int*   masks     = (const int*)d_in[2];
    const float* start_t   = (const float*)d_in[3];
    const float* end_t     = (const float*)d_in[4];
    const float* trans     = (const float*)d_in[5];
    float*       out       = (float*)d_out;

    int B = out_size;
    int S = in_sizes[1] / B;

    crf_prep<<<(KTAGS * (KTAGS / 2) + 255) / 256, 256>>>(trans);
    crf_main<<<B, NTH>>>(emissions, targets, masks, start_t, end_t, trans, out, S);
}

// round 8
// speedup vs baseline: 1.9828x; 1.1470x over previous
#include <cuda_runtime.h>
#include <cuda_fp16.h>
#include <cstdint>

#define KTAGS 256
#define NTH   256
#define SMAX  1024
#define LN2F  0.69314718055994531f

// ET column-pair-major: d_ETp[c*128 + i] = half2( exp(T[2i][c]), exp(T[2i+1][c]) )
__device__ __half2 d_ETp[KTAGS * (KTAGS / 2)];

__global__ void crf_prep(const float* __restrict__ trans) {
    int idx = blockIdx.x * blockDim.x + threadIdx.x;
    if (idx < KTAGS * (KTAGS / 2)) {
        int c = idx >> 7, i = idx & 127;
        float lo = expf(trans[(2 * i)     * KTAGS + c]);
        float hi = expf(trans[(2 * i + 1) * KTAGS + c]);
        d_ETp[idx] = __floats2half2_rn(lo, hi);
    }
}

__device__ __forceinline__ __half2 u2h(unsigned int u) { __half2 h; *(unsigned int*)&h = u; return h; }

__global__ __launch_bounds__(NTH, 1)
void crf_main(const float* __restrict__ emissions,
              const int* __restrict__ targets,
              const int* __restrict__ masks,
              const float* __restrict__ start_t,
              const float* __restrict__ end_t,
              const float* __restrict__ trans,
              float* __restrict__ out,
              int S)
{
    __shared__ __align__(16) unsigned int pvec[2][KTAGS / 2];  // p as half2, double-buffered
    __shared__ float pz[2];                                    // fp32 proxy (thread 0's p)
    __shared__ float red[8];
    __shared__ float rscr[NTH], cscr[NTH];
    __shared__ float num_smem;
    __shared__ int ms[SMAX];

    const int tid = threadIdx.x, b = blockIdx.x;
    const int lane = tid & 31, wid = tid >> 5;
    const int c = tid;                                  // my output column (tag)

    const float* emb  = emissions + (size_t)b * S * KTAGS;
    const int*   tg   = targets  + (size_t)b * S;
    const int*   mrow = masks    + (size_t)b * S;

    // ---- ET column c into registers: 128 half2 as 32 uint4 ----
    uint4 et4[32];
    {
        const uint4* etg = (const uint4*)(d_ETp + (size_t)c * 128);
        #pragma unroll
        for (int k = 0; k < 32; k++) et4[k] = etg[k];
    }

    // ---- masks into SMEM ----
    for (int t = tid; t < S && t < SMAX; t += NTH) ms[t] = mrow[t];

    // ---- Numerator ----
    float npart = 0.f; int cnt = 0;
    for (int t = tid; t < S; t += NTH) {
        int m = mrow[t] != 0; cnt += m;
        if (t >= 1 && m) {
            int pv = tg[t - 1], cu = tg[t];
            npart += trans[pv * KTAGS + cu] + emb[(size_t)t * KTAGS + cu];
        }
    }
    rscr[tid] = npart; cscr[tid] = (float)cnt;
    __syncthreads();
    if (tid == 0) {
        float tot = 0.f, cc = 0.f;
        for (int i = 0; i < NTH; i++) { tot += rscr[i]; cc += cscr[i]; }
        int seq_end = (int)cc - 1; int t0 = tg[0];
        num_smem = tot + start_t[t0] + emb[t0] + end_t[tg[seq_end]];
    }

    // ---- Init (t = 0): exact max-normalization + exact Sp once ----
    float s0 = start_t[c] + emb[c];
    float m = s0;
    #pragma unroll
    for (int o = 16; o > 0; o >>= 1) m = fmaxf(m, __shfl_xor_sync(0xffffffffu, m, o));
    if (lane == 0) red[wid] = m;
    __syncthreads();
    float M = red[0];
    #pragma unroll
    for (int w = 1; w < 8; w++) M = fmaxf(M, red[w]);
    float p = __expf(s0 - M);
    int ktot = 0;

    ((__half*)pvec[0])[c] = __float2half(p);
    // exact Sp at init -> proxy = Sp/256 (mean p), matching loop's steady-state semantics
    float psum = p;
    #pragma unroll
    for (int o = 16; o > 0; o >>= 1) psum += __shfl_xor_sync(0xffffffffu, psum, o);
    if (lane == 0) red[wid] = psum;
    __syncthreads();
    if (tid == 0) {
        float Sp = 0.f;
        #pragma unroll
        for (int w = 0; w < 8; w++) Sp += red[w];
        pz[0] = Sp * (1.0f / 256.0f);
    }

    // emission pipeline: ee = exp(e_t) for t=1, eraw = raw e for t=2
    float ee   = __expf(emb[(size_t)((1 < S) ? 1 : 0) * KTAGS + c]);
    float eraw = emb[(size_t)((2 < S) ? 2 : (S - 1)) * KTAGS + c];

    // ---- Forward recursion: one barrier per step, zero per-step reductions ----
    for (int t = 1; t < S; t++) {
        const int par = t & 1, pre = par ^ 1;
        __syncthreads();

        int tn = (t + 2 < S) ? (t + 2) : (S - 1);
        float eraw2 = emb[(size_t)tn * KTAGS + c];
        int msk = (t < SMAX) ? ms[t] : mrow[t];

        // lag-1 proxy normalizer: single broadcast LDS + bit ops
        float P = pz[pre];
        unsigned int sb = __float_as_uint(P);
        int ke = (int)(sb >> 23) - 118;                                   // ilogb+9
        float sf = __uint_as_float((unsigned int)(245 - (int)(sb >> 23)) << 23);  // 2^-ke

        // matvec: ssum_c = sum_i p_i * ET[i][c], 8 independent fp16 chains
        __half2 a0 = u2h(0u), a1 = u2h(0u), a2 = u2h(0u), a3 = u2h(0u);
        __half2 a4 = u2h(0u), a5 = u2h(0u), a6 = u2h(0u), a7 = u2h(0u);
        const uint4* pv = (const uint4*)pvec[pre];      // 32 broadcast uint4
        #pragma unroll
        for (int k = 0; k < 32; k += 2) {
            uint4 q0 = pv[k];
            uint4 q1 = pv[k + 1];
            a0 = __hfma2(u2h(et4[k].x),     u2h(q0.x), a0);
            a1 = __hfma2(u2h(et4[k].y),     u2h(q0.y), a1);
            a2 = __hfma2(u2h(et4[k].z),     u2h(q0.z), a2);
            a3 = __hfma2(u2h(et4[k].w),     u2h(q0.w), a3);
            a4 = __hfma2(u2h(et4[k + 1].x), u2h(q1.x), a4);
            a5 = __hfma2(u2h(et4[k + 1].y), u2h(q1.y), a5);
            a6 = __hfma2(u2h(et4[k + 1].z), u2h(q1.z), a6);
            a7 = __hfma2(u2h(et4[k + 1].w), u2h(q1.w), a7);
        }
        __half2 sA = __hadd2(__hadd2(a0, a1), __hadd2(a2, a3));
        __half2 sB = __hadd2(__hadd2(a4, a5), __hadd2(a6, a7));
        float2 fA = __half22float2(sA);
        float2 fB = __half22float2(sB);
        float ssum = (fA.x + fA.y) + (fB.x + fB.y);

        float q = ssum * ee;
        if (msk) { p = q * sf; ktot += ke; }

        ((__half*)pvec[par])[c] = __float2half(p);
        if (tid == 0) pz[par] = p;                      // fp32 proxy for next step

        // off-critical-path: emission exp for step t+1
        ee = __expf(eraw);
        eraw = eraw2;
    }

    // ---- Final: denominator = M + ktot*ln2 + log(Sigma p * exp(end)) ----
    float v = p * __expf(end_t[c]);
    #pragma unroll
    for (int o = 16; o > 0; o >>= 1) v += __shfl_xor_sync(0xffffffffu, v, o);
    if (lane == 0) red[wid] = v;
    __syncthreads();
    if (tid == 0) {
        float tot = 0.f;
        #pragma unroll
        for (int w = 0; w < 8; w++) tot += red[w];
        out[b] = num_smem - (M + (float)ktot * LN2F + __logf(tot));
    }
}

extern "C" void kernel_launch(void* const* d_in, const int* in_sizes, int n_in,
                              void* d_out, int out_size) {
    const float* emissions = (const float*)d_in[0];
    const int*   targets   = (const int*)d_in[1];
    const int*   masks     = (const int*)d_in[2];
    const float* start_t   = (const float*)d_in[3];
    const float* end_t     = (const float*)d_in[4];
    const float* trans     = (const float*)d_in[5];
    float*       out       = (float*)d_out;

    int B = out_size;
    int S = in_sizes[1] / B;

    crf_prep<<<(KTAGS * (KTAGS / 2) + 255) / 256, 256>>>(trans);
    crf_main<<<B, NTH>>>(emissions, targets, masks, start_t, end_t, trans, out, S);
}